// round 9
// baseline (speedup 1.0000x reference)
#include <cuda_runtime.h>
#include <cuda_bf16.h>
#include <cstdint>

#define BTOT 16384
#define PFULL 4416          // 64 z + 256 feat + 4096 zz (full)
#define PW2   2624          // 64 z + 256 feat + 2304 zz (8-aligned tri groups)
#define NGRP  288
#define NCH   41            // PW2 / 64
#define SQRTK 11.313708498984761f

__device__ float g_Wpart[2][64 * PFULL];
__device__ __align__(16) __nv_bfloat16 g_Wh[64 * PW2];
__device__ __align__(16) __nv_bfloat16 g_Wl[64 * PW2];
__device__ float g_csq[64];
__device__ float g_bsum[64];
__device__ uchar2 g_gij[NGRP];

// -------- prep stage 1: fold over K (split-k, 2 partials) --------------------
__global__ void prep_fold1(const float* __restrict__ qzw,
                           const float* __restrict__ qfw,
                           const float* __restrict__ qg,
                           const float* __restrict__ cq) {
  __shared__ float cq_s[64 * 64];
  const int tid = threadIdx.x;
  const int kbase = blockIdx.y * 64;
  for (int i = tid; i < 1024; i += 256) {
    int row = i >> 4, q = i & 15;
    *(float4*)(cq_s + row * 64 + q * 4) =
        *(const float4*)(cq + row * 128 + kbase + q * 4);
  }
  __syncthreads();

  const int p  = blockIdx.x * 32 + (tid & 7) * 4;
  const int ng = tid >> 3;            // 32 groups x 2 charts
  const float* src; int stride, off;
  if (p < 64)       { src = qzw; stride = 64;   off = p; }
  else if (p < 320) { src = qfw; stride = 256;  off = p - 64; }
  else              { src = qg;  stride = 4096; off = p - 320; }
  src += (size_t)kbase * stride;

  float acc[2][4] = {};
  for (int k0 = 0; k0 < 64; k0 += 8) {
    float4 wv[8];
#pragma unroll
    for (int kk = 0; kk < 8; ++kk)
      wv[kk] = *(const float4*)(src + (size_t)(k0 + kk) * stride + off);
#pragma unroll
    for (int kk = 0; kk < 8; ++kk) {
#pragma unroll
      for (int j = 0; j < 2; ++j) {
        float cv = cq_s[(ng * 2 + j) * 64 + k0 + kk];
        acc[j][0] = fmaf(cv, wv[kk].x, acc[j][0]);
        acc[j][1] = fmaf(cv, wv[kk].y, acc[j][1]);
        acc[j][2] = fmaf(cv, wv[kk].z, acc[j][2]);
        acc[j][3] = fmaf(cv, wv[kk].w, acc[j][3]);
      }
    }
  }
#pragma unroll
  for (int j = 0; j < 2; ++j)
    *(float4*)(g_Wpart[blockIdx.y] + (size_t)(ng * 2 + j) * PFULL + p) =
        *(float4*)acc[j];
}

// ------- prep stage 2: sum partials, tri-fold, hi/lo split, tables ----------
__global__ void prep_fold2() {
  const int tid = threadIdx.x;
  const int pl = blockIdx.x * 64 + (tid & 63);
  const int ng = tid >> 6;                 // 4 groups x 16 charts
  int srcp = -1, srcq = -1;
  if (pl < 320) {
    srcp = pl;
  } else {
    int t = pl - 320;
    int g = t >> 3, w8 = t & 7;
    int i = 0, cum = 0;
    for (int ii = 0; ii < 64; ++ii) {
      int cnt = 8 - (ii >> 3);
      if (g < cum + cnt) { i = ii; break; }
      cum += cnt;
    }
    int b = (i >> 3) + (g - cum);
    int j = b * 8 + w8;
    if (ng == 0 && w8 == 0)
      g_gij[g] = make_uchar2((unsigned char)i, (unsigned char)(b * 8));
    if (j >= i) {
      srcp = 320 + i * 64 + j;
      srcq = (j > i) ? (320 + j * 64 + i) : -1;
    }
  }
#pragma unroll 4
  for (int jj = 0; jj < 16; ++jj) {
    int n = ng * 16 + jj;
    float v = 0.f;
    if (srcp >= 0) {
      v = g_Wpart[0][(size_t)n * PFULL + srcp] +
          g_Wpart[1][(size_t)n * PFULL + srcp];
      if (srcq >= 0)
        v += g_Wpart[0][(size_t)n * PFULL + srcq] +
             g_Wpart[1][(size_t)n * PFULL + srcq];
    }
    __nv_bfloat16 h = __float2bfloat16(v);
    g_Wh[(size_t)n * PW2 + pl] = h;
    g_Wl[(size_t)n * PW2 + pl] = __float2bfloat16(v - __bfloat162float(h));
  }
}

__global__ void prep_small(const float* __restrict__ cq,
                           const float* __restrict__ qzb,
                           const float* __restrict__ qfb) {
  int n = threadIdx.x;
  if (n >= 64) return;
  const float* r = cq + n * 128;
  float cs = 0.f, bs = 0.f;
  for (int d = 0; d < 64; ++d) cs = fmaf(r[d], r[d], cs);
  for (int k = 0; k < 128; ++k) bs = fmaf(r[k], qzb[k] + qfb[k], bs);
  g_csq[n] = cs;
  g_bsum[n] = bs;
}

// --------------------------- main kernel ------------------------------------
// 64 rows/CTA, grid 256, 2 CTAs/SM, warp-specialized (4 mma + 4 producer).
#define O_ZS   0             // float [64][68] = 17408
#define O_CS   17408         // float [64][64] = 16384
#define O_GIJ  33792         // uchar2[288] = 576
#define O_ZSQ  34368
#define O_CSQ  34624
#define O_BSM  34880
#define O_RMX  35136
#define O_RIV  35392
#define O_XH   35648         // bf16 [2][64][72] = 18432  (Sc overlaps)
#define O_XL   54080         // bf16 [2][64][72] = 18432  (zcS overlaps)
#define O_WH   72512         // bf16 [2][64][72] = 18432
#define O_WL   90944         // bf16 [2][64][72] = 18432
#define SMEMB  109376

__device__ __forceinline__ void mma16816(float* c, const uint32_t* a,
                                         const uint32_t* b) {
  asm volatile(
      "mma.sync.aligned.m16n8k16.row.col.f32.bf16.bf16.f32 "
      "{%0,%1,%2,%3},{%4,%5,%6,%7},{%8,%9},{%0,%1,%2,%3};"
      : "+f"(c[0]), "+f"(c[1]), "+f"(c[2]), "+f"(c[3])
      : "r"(a[0]), "r"(a[1]), "r"(a[2]), "r"(a[3]), "r"(b[0]), "r"(b[1]));
}
__device__ __forceinline__ void ldsm4(uint32_t* r, uint32_t saddr) {
  asm volatile(
      "ldmatrix.sync.aligned.m8n8.x4.shared.b16 {%0,%1,%2,%3},[%4];"
      : "=r"(r[0]), "=r"(r[1]), "=r"(r[2]), "=r"(r[3]) : "r"(saddr));
}
__device__ __forceinline__ void bar_sync(int id) {
  asm volatile("bar.sync %0, 256;" :: "r"(id) : "memory");
}
__device__ __forceinline__ void bar_arrive(int id) {
  asm volatile("bar.arrive %0, 256;" :: "r"(id) : "memory");
}
__device__ __forceinline__ void split_store(char* xh, char* xl, const float* v) {
  uint32_t ph[4], plo[4];
#pragma unroll
  for (int j = 0; j < 4; ++j) {
    __nv_bfloat162 h2 = __float22bfloat162_rn(make_float2(v[2 * j], v[2 * j + 1]));
    ph[j] = *(uint32_t*)&h2;
    __nv_bfloat162 l2 = __float22bfloat162_rn(
        make_float2(v[2 * j] - __low2float(h2), v[2 * j + 1] - __high2float(h2)));
    plo[j] = *(uint32_t*)&l2;
  }
  *(uint4*)xh = *(uint4*)ph;
  *(uint4*)xl = *(uint4*)plo;
}

__global__ void __launch_bounds__(256, 2)
atlas_main(const float* __restrict__ z, const float* __restrict__ feat,
           const float* __restrict__ cq, float* __restrict__ out,
           int out_size) {
  extern __shared__ char sm[];
  float* zs   = (float*)(sm + O_ZS);    // stride 68
  float* cs   = (float*)(sm + O_CS);    // stride 64
  uchar2* gij = (uchar2*)(sm + O_GIJ);
  float* zsq  = (float*)(sm + O_ZSQ);
  float* csqs = (float*)(sm + O_CSQ);
  float* bsm  = (float*)(sm + O_BSM);
  float* rmx  = (float*)(sm + O_RMX);
  float* riv  = (float*)(sm + O_RIV);
  float* Sc   = (float*)(sm + O_XH);    // stride 68, post-loop overlap
  float* zcS  = (float*)(sm + O_XL);    // stride 64, post-loop overlap
  __nv_bfloat16* Xh = (__nv_bfloat16*)(sm + O_XH);
  __nv_bfloat16* Xl = (__nv_bfloat16*)(sm + O_XL);
  __nv_bfloat16* Wh = (__nv_bfloat16*)(sm + O_WH);
  __nv_bfloat16* Wl = (__nv_bfloat16*)(sm + O_WL);

  const int tid = threadIdx.x, lane = tid & 31, w = tid >> 5;
  const int gid = lane >> 2, tg = lane & 3;
  const int r0 = blockIdx.x * 64;
  const uint32_t smb = (uint32_t)__cvta_generic_to_shared(sm);

  for (int i = tid; i < 1024; i += 256) {          // z: 64 rows x 16 float4
    int row = i >> 4, q = i & 15;
    *(float4*)(zs + row * 68 + q * 4) =
        ((const float4*)(z + (size_t)(r0 + row) * 64))[q];
  }
  for (int i = tid; i < 1024; i += 256) {          // centers 64x64
    int n = i >> 4, q = i & 15;
    *(float4*)(cs + n * 64 + q * 4) = *(const float4*)(cq + n * 128 + q * 4);
  }
  for (int i = tid; i < NGRP; i += 256) gij[i] = g_gij[i];
  if (tid < 64) { csqs[tid] = g_csq[tid]; bsm[tid] = g_bsum[tid]; }
  __syncthreads();

  float zc[32];
  float accs[4][2][4] = {};

  if (w < 4) {
    // =================== consumer: LDSM + MMA only ===================
    if (tid < 64) {
      float s = 0.f;
      const float* zr = zs + tid * 68;
      for (int d = 0; d < 64; ++d) s = fmaf(zr[d], zr[d], s);
      zsq[tid] = s;
    }
    const int nb = w * 16;
    const uint32_t aoff = ((lane & 15) * 72 + (lane >> 4) * 8) * 2;
    const uint32_t boff =
        (((((lane >> 4) << 3)) + (lane & 7)) * 72 + ((lane >> 3) & 1) * 8) * 2;
    const uint32_t XHb = smb + O_XH + aoff;
    const uint32_t XLb = smb + O_XL + aoff;
    const uint32_t WHb = smb + O_WH + nb * 144 + boff;
    const uint32_t WLb = smb + O_WL + nb * 144 + boff;

    for (int c = 0; c < NCH; ++c) {
      const int b = c & 1;
      bar_sync(1 + b);                      // wait full
      const uint32_t xh0 = XHb + b * 9216, xl0 = XLb + b * 9216;
      const uint32_t wh0 = WHb + b * 9216, wl0 = WLb + b * 9216;
#pragma unroll
      for (int kh = 0; kh < 4; ++kh) {
        const uint32_t kb = kh * 32;
        uint32_t bh[4], bl[4];
        ldsm4(bh, wh0 + kb);
        ldsm4(bl, wl0 + kb);
#pragma unroll
        for (int mt = 0; mt < 4; ++mt) {
          uint32_t ah[4], al[4];
          ldsm4(ah, xh0 + mt * 2304 + kb);
          ldsm4(al, xl0 + mt * 2304 + kb);
#pragma unroll
          for (int nt = 0; nt < 2; ++nt) {
            mma16816(accs[mt][nt], ah, bh + nt * 2);
            mma16816(accs[mt][nt], ah, bl + nt * 2);
            mma16816(accs[mt][nt], al, bh + nt * 2);
          }
        }
      }
      bar_arrive(3 + b);                    // signal empty
    }
  } else {
    // =================== producer: X-gen + W copy + zc ===================
    const int ptid = tid - 128;
    const int xr = ptid >> 1, half = ptid & 1;
    const float* zrow = zs + xr * 68;
    const int wn = ptid >> 1, wseg = half * 32;   // W copy role
    const float* cbase = cs + (half * 32) * 64;
#pragma unroll
    for (int q = 0; q < 32; ++q) zc[q] = 0.f;

    for (int c = 0; c < NCH; ++c) {
      const int b = c & 1;
      if (c >= 2) bar_sync(3 + b);          // wait empty
      char* xhb = sm + O_XH + b * 9216 + xr * 144;
      char* xlb = sm + O_XL + b * 9216 + xr * 144;
#pragma unroll
      for (int g = 0; g < 4; ++g) {
        const int j0 = half * 32 + g * 8;
        float v[8];
        if (c == 0) {
          float4 u0 = *(const float4*)(zrow + j0);
          float4 u1 = *(const float4*)(zrow + j0 + 4);
          v[0] = u0.x; v[1] = u0.y; v[2] = u0.z; v[3] = u0.w;
          v[4] = u1.x; v[5] = u1.y; v[6] = u1.z; v[7] = u1.w;
        } else if (c < 5) {
          const float* fp = feat + (size_t)(r0 + xr) * 256 + (c * 64 - 64) + j0;
          float4 u0 = *(const float4*)fp;
          float4 u1 = *(const float4*)(fp + 4);
          v[0] = u0.x; v[1] = u0.y; v[2] = u0.z; v[3] = u0.w;
          v[4] = u1.x; v[5] = u1.y; v[6] = u1.z; v[7] = u1.w;
        } else {
          uchar2 ij = gij[(c - 5) * 8 + half * 4 + g];
          float sc = zrow[ij.x];
          float4 u0 = *(const float4*)(zrow + ij.y);
          float4 u1 = *(const float4*)(zrow + ij.y + 4);
          v[0] = sc * u0.x; v[1] = sc * u0.y; v[2] = sc * u0.z; v[3] = sc * u0.w;
          v[4] = sc * u1.x; v[5] = sc * u1.y; v[6] = sc * u1.z; v[7] = sc * u1.w;
        }
        split_store(xhb + j0 * 2, xlb + j0 * 2, v);
      }
      {
        const __nv_bfloat16* gh = g_Wh + (size_t)wn * PW2 + c * 64 + wseg;
        const __nv_bfloat16* gl = g_Wl + (size_t)wn * PW2 + c * 64 + wseg;
        uint4 h0 = *(const uint4*)gh, h1 = *(const uint4*)(gh + 8);
        uint4 h2 = *(const uint4*)(gh + 16), h3 = *(const uint4*)(gh + 24);
        uint4 l0 = *(const uint4*)gl, l1 = *(const uint4*)(gl + 8);
        uint4 l2 = *(const uint4*)(gl + 16), l3 = *(const uint4*)(gl + 24);
        __nv_bfloat16* dh = Wh + b * 4608 + wn * 72 + wseg;
        __nv_bfloat16* dl = Wl + b * 4608 + wn * 72 + wseg;
        *(uint4*)dh = h0; *(uint4*)(dh + 8) = h1;
        *(uint4*)(dh + 16) = h2; *(uint4*)(dh + 24) = h3;
        *(uint4*)dl = l0; *(uint4*)(dl + 8) = l1;
        *(uint4*)(dl + 16) = l2; *(uint4*)(dl + 24) = l3;
      }
      bar_arrive(1 + b);                    // signal full
      // overlapped fp32 z.c slice (2 dims per chunk, dims 0..63)
      if (c < 32) {
        const int d0 = 2 * c;
        float a0 = zrow[d0], a1 = zrow[d0 + 1];
#pragma unroll
        for (int q = 0; q < 32; ++q) {
          float2 cc = *(const float2*)(cbase + q * 64 + d0);
          zc[q] = fmaf(a0, cc.x, fmaf(a1, cc.y, zc[q]));
        }
      }
    }
  }
  __syncthreads();   // all chunks consumed; X/W buffers now dead

  if (w < 4) {
    // consumer: dump gem into Sc
    const int nb = w * 16;
#pragma unroll
    for (int mt = 0; mt < 4; ++mt)
#pragma unroll
      for (int nt = 0; nt < 2; ++nt)
#pragma unroll
        for (int q = 0; q < 4; ++q) {
          const int row = mt * 16 + gid + (q >> 1) * 8;
          const int col = nb + tg * 2 + nt * 8 + (q & 1);
          Sc[row * 68 + col] = accs[mt][nt][q];
        }
  } else {
    // producer: dump zc into zcS
    const int ptid = tid - 128;
    const int xr = ptid >> 1, half = ptid & 1;
#pragma unroll
    for (int q = 0; q < 32; ++q) zcS[xr * 64 + half * 32 + q] = zc[q];
  }
  __syncthreads();

  // ---- scoring: all 256 threads, 16 cells each ----
  {
    const int row = tid >> 2;
    const float zq = zsq[row];
    const float tau = fmaxf(SQRTK * fmaxf(1.f - zq, 1e-3f) * 0.5f, 0.01f);
    const float invlam = (1.f - fminf(zq, 0.999f) + 1e-3f) * 0.5f;
    const float dn1 = 1.f - zq;
#pragma unroll 4
    for (int k = 0; k < 16; ++k) {
      const int col = (tid & 3) * 16 + k;
      const float gem = Sc[row * 68 + col];
      const float cq2 = csqs[col];
      const float dsq = zq + cq2 - 2.f * zcS[row * 64 + col];
      const float denom = dn1 * (1.f - cq2) + 1e-3f;
      float arg = fmaxf(1.f + 2.f * dsq / denom, 1.001f);
      float dist = logf(arg + sqrtf((arg + 1.f) * (arg - 1.f)));
      Sc[row * 68 + col] =
          -dist / tau + (gem + bsm[col]) * invlam * (1.f / SQRTK);
    }
  }
  __syncthreads();

  // ---- softmax + argmax ----
  const bool has_k = (out_size >= BTOT * 64 + BTOT);
  if (tid < 64) {
    float m = -1e30f; int am = 0;
    const float* sr = Sc + tid * 68;
    for (int n = 0; n < 64; ++n) {
      float v = sr[n];
      if (v > m) { m = v; am = n; }
    }
    float s = 0.f;
    for (int n = 0; n < 64; ++n) s += __expf(sr[n] - m);
    rmx[tid] = m;
    riv[tid] = 1.f / s;
    if (has_k) out[BTOT * 64 + r0 + tid] = (float)am;
  }
  __syncthreads();
  for (int i = tid; i < 4096; i += 256) {
    int r = i >> 6, n = i & 63;
    out[(size_t)(r0 + r) * 64 + n] = __expf(Sc[r * 68 + n] - rmx[r]) * riv[r];
  }
}

// ----------------------------------------------------------------------------
extern "C" void kernel_launch(void* const* d_in, const int* in_sizes, int n_in,
                              void* d_out, int out_size) {
  const float* z    = (const float*)d_in[0];
  const float* feat = (const float*)d_in[1];
  const float* qzw  = (const float*)d_in[2];
  const float* qzb  = (const float*)d_in[3];
  const float* qfw  = (const float*)d_in[4];
  const float* qfb  = (const float*)d_in[5];
  const float* qg   = (const float*)d_in[6];
  const float* cq   = (const float*)d_in[7];
  float* out = (float*)d_out;

  prep_fold1<<<dim3(PFULL / 32, 2), 256>>>(qzw, qfw, qg, cq);
  prep_fold2<<<NCH, 256>>>();
  prep_small<<<1, 64>>>(cq, qzb, qfb);
  cudaFuncSetAttribute(atlas_main, cudaFuncAttributeMaxDynamicSharedMemorySize,
                       SMEMB);
  atlas_main<<<BTOT / 64, 256, SMEMB>>>(z, feat, cq, out, out_size);
}